// round 1
// baseline (speedup 1.0000x reference)
#include <cuda_runtime.h>
#include <cstddef>

// Problem constants (fixed by the reference)
#define BATCH 32
#define NQ    1024   // W*H
#define LSEQ  512
#define DIM   768

// Scratch (device globals — allocation-free per harness rules)
__device__ float g_qp[(size_t)BATCH * NQ * DIM];    // 100.7 MB
__device__ float g_kp[(size_t)BATCH * LSEQ * DIM];  //  50.3 MB
__device__ float g_vp[(size_t)BATCH * LSEQ * DIM];  //  50.3 MB
__device__ float g_s [(size_t)BATCH * NQ * LSEQ];   //  67.1 MB

// ---------------------------------------------------------------------------
// C[M,N] = A[M,K] @ B[N,K]^T (+ bias[N]); batched via blockIdx.z with strides.
// A row-major lda=K, B row-major ldb=K (both K-major: "NT" gemm).
// Tile: 128x128x8, 256 threads, 8x8 per thread. All dims divide exactly.
// ---------------------------------------------------------------------------
__global__ __launch_bounds__(256) void sgemm_nt(
    const float* __restrict__ A, const float* __restrict__ Bm,
    const float* __restrict__ bias, float* __restrict__ C,
    int K, int N, size_t sA, size_t sB, size_t sC)
{
    __shared__ float As[8][128];
    __shared__ float Bs[8][128];

    const float* Ab = A  + (size_t)blockIdx.z * sA + (size_t)blockIdx.y * 128 * K;
    const float* Bb = Bm + (size_t)blockIdx.z * sB + (size_t)blockIdx.x * 128 * K;
    float*       Cb = C  + (size_t)blockIdx.z * sC;

    const int tid  = threadIdx.x;
    const int lrow = tid >> 1;        // 0..127
    const int lcol = (tid & 1) * 4;   // 0 or 4
    const int ty   = tid >> 4;        // 0..15
    const int tx   = tid & 15;        // 0..15

    float acc[8][8];
    #pragma unroll
    for (int i = 0; i < 8; i++)
        #pragma unroll
        for (int j = 0; j < 8; j++) acc[i][j] = 0.f;

    for (int k0 = 0; k0 < K; k0 += 8) {
        float4 av = *(const float4*)(Ab + (size_t)lrow * K + k0 + lcol);
        float4 bv = *(const float4*)(Bb + (size_t)lrow * K + k0 + lcol);
        As[lcol + 0][lrow] = av.x; As[lcol + 1][lrow] = av.y;
        As[lcol + 2][lrow] = av.z; As[lcol + 3][lrow] = av.w;
        Bs[lcol + 0][lrow] = bv.x; Bs[lcol + 1][lrow] = bv.y;
        Bs[lcol + 2][lrow] = bv.z; Bs[lcol + 3][lrow] = bv.w;
        __syncthreads();

        #pragma unroll
        for (int kk = 0; kk < 8; kk++) {
            float a[8], b[8];
            #pragma unroll
            for (int i = 0; i < 8; i++) a[i] = As[kk][ty * 8 + i];
            #pragma unroll
            for (int j = 0; j < 8; j++) b[j] = Bs[kk][tx * 8 + j];
            #pragma unroll
            for (int i = 0; i < 8; i++)
                #pragma unroll
                for (int j = 0; j < 8; j++) acc[i][j] += a[i] * b[j];
        }
        __syncthreads();
    }

    float bvals[8];
    #pragma unroll
    for (int j = 0; j < 8; j++)
        bvals[j] = bias ? bias[blockIdx.x * 128 + tx * 8 + j] : 0.f;

    #pragma unroll
    for (int i = 0; i < 8; i++) {
        size_t crow = (size_t)blockIdx.y * 128 + ty * 8 + i;
        float* dst = Cb + crow * N + blockIdx.x * 128 + tx * 8;
        float4 lo = make_float4(acc[i][0] + bvals[0], acc[i][1] + bvals[1],
                                acc[i][2] + bvals[2], acc[i][3] + bvals[3]);
        float4 hi = make_float4(acc[i][4] + bvals[4], acc[i][5] + bvals[5],
                                acc[i][6] + bvals[6], acc[i][7] + bvals[7]);
        *(float4*)dst       = lo;
        *(float4*)(dst + 4) = hi;
    }
}

// ---------------------------------------------------------------------------
// C[M,N] = A[M,K] @ B[K,N]; batched. A row-major lda=K, B row-major ldb=N.
// ---------------------------------------------------------------------------
__global__ __launch_bounds__(256) void sgemm_nn(
    const float* __restrict__ A, const float* __restrict__ Bm,
    float* __restrict__ C, int K, int N, size_t sA, size_t sB, size_t sC)
{
    __shared__ float As[8][128];
    __shared__ float Bs[8][128];

    const float* Ab = A  + (size_t)blockIdx.z * sA + (size_t)blockIdx.y * 128 * K;
    const float* Bb = Bm + (size_t)blockIdx.z * sB + blockIdx.x * 128;
    float*       Cb = C  + (size_t)blockIdx.z * sC;

    const int tid  = threadIdx.x;
    const int arow = tid >> 1;        // 0..127
    const int acol = (tid & 1) * 4;   // 0 or 4
    const int brow = tid >> 5;        // 0..7
    const int bcol = (tid & 31) * 4;  // 0..124
    const int ty   = tid >> 4;
    const int tx   = tid & 15;

    float acc[8][8];
    #pragma unroll
    for (int i = 0; i < 8; i++)
        #pragma unroll
        for (int j = 0; j < 8; j++) acc[i][j] = 0.f;

    for (int k0 = 0; k0 < K; k0 += 8) {
        float4 av = *(const float4*)(Ab + (size_t)arow * K + k0 + acol);
        As[acol + 0][arow] = av.x; As[acol + 1][arow] = av.y;
        As[acol + 2][arow] = av.z; As[acol + 3][arow] = av.w;
        float4 bv = *(const float4*)(Bb + (size_t)(k0 + brow) * N + bcol);
        *(float4*)&Bs[brow][bcol] = bv;
        __syncthreads();

        #pragma unroll
        for (int kk = 0; kk < 8; kk++) {
            float a[8], b[8];
            #pragma unroll
            for (int i = 0; i < 8; i++) a[i] = As[kk][ty * 8 + i];
            #pragma unroll
            for (int j = 0; j < 8; j++) b[j] = Bs[kk][tx * 8 + j];
            #pragma unroll
            for (int i = 0; i < 8; i++)
                #pragma unroll
                for (int j = 0; j < 8; j++) acc[i][j] += a[i] * b[j];
        }
        __syncthreads();
    }

    #pragma unroll
    for (int i = 0; i < 8; i++) {
        size_t crow = (size_t)blockIdx.y * 128 + ty * 8 + i;
        float* dst = Cb + crow * N + blockIdx.x * 128 + tx * 8;
        *(float4*)dst       = make_float4(acc[i][0], acc[i][1], acc[i][2], acc[i][3]);
        *(float4*)(dst + 4) = make_float4(acc[i][4], acc[i][5], acc[i][6], acc[i][7]);
    }
}

// ---------------------------------------------------------------------------
// In-place scaled softmax over rows of length 512. One warp per row.
// ---------------------------------------------------------------------------
__global__ __launch_bounds__(256) void softmax_rows(float* __restrict__ S, float scale)
{
    const int row  = blockIdx.x * 8 + (threadIdx.x >> 5);
    const int lane = threadIdx.x & 31;
    float4* r4 = (float4*)(S + (size_t)row * LSEQ) + lane;

    float4 v[4];
    #pragma unroll
    for (int i = 0; i < 4; i++) {
        v[i] = r4[32 * i];
        v[i].x *= scale; v[i].y *= scale; v[i].z *= scale; v[i].w *= scale;
    }

    float mx = -3.4e38f;
    #pragma unroll
    for (int i = 0; i < 4; i++)
        mx = fmaxf(mx, fmaxf(fmaxf(v[i].x, v[i].y), fmaxf(v[i].z, v[i].w)));
    #pragma unroll
    for (int o = 16; o > 0; o >>= 1)
        mx = fmaxf(mx, __shfl_xor_sync(0xffffffffu, mx, o));

    float sum = 0.f;
    #pragma unroll
    for (int i = 0; i < 4; i++) {
        v[i].x = __expf(v[i].x - mx); v[i].y = __expf(v[i].y - mx);
        v[i].z = __expf(v[i].z - mx); v[i].w = __expf(v[i].w - mx);
        sum += v[i].x + v[i].y + v[i].z + v[i].w;
    }
    #pragma unroll
    for (int o = 16; o > 0; o >>= 1)
        sum += __shfl_xor_sync(0xffffffffu, sum, o);

    const float inv = 1.0f / sum;
    #pragma unroll
    for (int i = 0; i < 4; i++) {
        v[i].x *= inv; v[i].y *= inv; v[i].z *= inv; v[i].w *= inv;
        r4[32 * i] = v[i];
    }
}

// ---------------------------------------------------------------------------
// Launch: qp/kp/vp projections -> scores -> softmax -> output
// ---------------------------------------------------------------------------
extern "C" void kernel_launch(void* const* d_in, const int* in_sizes, int n_in,
                              void* d_out, int out_size)
{
    const float* q   = (const float*)d_in[0];  // [B,768,32,32] == [32768,768] row-major
    const float* k   = (const float*)d_in[1];  // [B,512,768]   == [16384,768]
    const float* v   = (const float*)d_in[2];
    const float* q_w = (const float*)d_in[3];  // [768,768]
    const float* q_b = (const float*)d_in[4];
    const float* k_w = (const float*)d_in[5];
    const float* k_b = (const float*)d_in[6];
    const float* v_w = (const float*)d_in[7];
    const float* v_b = (const float*)d_in[8];
    float* out = (float*)d_out;                // [B,1024,768] row-major (raw reshape)

    float *qp, *kp, *vp, *s;
    cudaGetSymbolAddress((void**)&qp, g_qp);
    cudaGetSymbolAddress((void**)&kp, g_kp);
    cudaGetSymbolAddress((void**)&vp, g_vp);
    cudaGetSymbolAddress((void**)&s,  g_s);

    // Projections: C[M,768] = X[M,768] @ W[768,768]^T + b
    sgemm_nt<<<dim3(DIM / 128, (BATCH * NQ) / 128, 1), 256>>>(
        q, q_w, q_b, qp, DIM, DIM, 0, 0, 0);
    sgemm_nt<<<dim3(DIM / 128, (BATCH * LSEQ) / 128, 1), 256>>>(
        k, k_w, k_b, kp, DIM, DIM, 0, 0, 0);
    sgemm_nt<<<dim3(DIM / 128, (BATCH * LSEQ) / 128, 1), 256>>>(
        v, v_w, v_b, vp, DIM, DIM, 0, 0, 0);

    // Scores: S[b] = qp[b] @ kp[b]^T   (1024x512, K=768)
    sgemm_nt<<<dim3(LSEQ / 128, NQ / 128, BATCH), 256>>>(
        qp, kp, nullptr, s, DIM, LSEQ,
        (size_t)NQ * DIM, (size_t)LSEQ * DIM, (size_t)NQ * LSEQ);

    // Softmax with scale = 1/sqrt(768)
    softmax_rows<<<(BATCH * NQ) / 8, 256>>>(s, 0.03608439182435161f);

    // Output: O[b] = P[b] @ vp[b]   (1024x768, K=512)
    sgemm_nn<<<dim3(DIM / 128, NQ / 128, BATCH), 256>>>(
        s, vp, out, LSEQ, DIM,
        (size_t)NQ * LSEQ, (size_t)LSEQ * DIM, (size_t)NQ * DIM);
}

// round 2
// speedup vs baseline: 2.4779x; 2.4779x over previous
#include <cuda_runtime.h>
#include <cstddef>

#define BATCH 32
#define NQ    1024
#define LSEQ  512
#define DIM   768
#define KT    32      // K-tile
#define SPAD  136     // smem row stride in words (mod 32 == 8 -> conflict-free frags)

__device__ float g_qp[(size_t)BATCH * NQ * DIM];
__device__ float g_kp[(size_t)BATCH * LSEQ * DIM];
__device__ float g_vp[(size_t)BATCH * LSEQ * DIM];
__device__ float g_s [(size_t)BATCH * NQ * LSEQ];

__device__ __forceinline__ unsigned f2tf32(float x) {
    unsigned r;
    asm("cvt.rna.tf32.f32 %0, %1;" : "=r"(r) : "f"(x));
    return r;
}

__device__ __forceinline__ void mma_tf32(float c[4],
    unsigned a0, unsigned a1, unsigned a2, unsigned a3,
    unsigned b0, unsigned b1)
{
    asm("mma.sync.aligned.m16n8k8.row.col.f32.tf32.tf32.f32 "
        "{%0,%1,%2,%3},{%4,%5,%6,%7},{%8,%9},{%0,%1,%2,%3};"
        : "+f"(c[0]), "+f"(c[1]), "+f"(c[2]), "+f"(c[3])
        : "r"(a0), "r"(a1), "r"(a2), "r"(a3), "r"(b0), "r"(b1));
}

// ---------------------------------------------------------------------------
// C[M,N] = A[M,K] @ B[N,K]^T (+bias[N]). A,B row-major (K contiguous).
// Block 128x128xKT, 256 thr, warp grid 2x4, warp tile 64x32 (4x4 m16n8k8).
// ---------------------------------------------------------------------------
__global__ __launch_bounds__(256) void tgemm_nt(
    const float* __restrict__ A, const float* __restrict__ Bm,
    const float* __restrict__ bias, float* __restrict__ C,
    int K, int N, size_t sA, size_t sB, size_t sC)
{
    __shared__ unsigned As[KT][SPAD];
    __shared__ unsigned Bs[KT][SPAD];

    const float* Ab = A  + (size_t)blockIdx.z * sA + (size_t)blockIdx.y * 128 * K;
    const float* Bb = Bm + (size_t)blockIdx.z * sB + (size_t)blockIdx.x * 128 * K;
    float*       Cb = C  + (size_t)blockIdx.z * sC;

    const int tid  = threadIdx.x;
    const int lane = tid & 31;
    const int wid  = tid >> 5;
    const int wm   = (wid >> 2) * 64;   // warp m offset
    const int wn   = (wid & 3) * 32;    // warp n offset
    const int gid  = lane >> 2;         // 0..7
    const int tig  = lane & 3;          // 0..3

    const int lrow = tid >> 1;          // 0..127
    const int lk   = (tid & 1) * 16;    // 0 or 16

    float acc[4][4][4];
    #pragma unroll
    for (int i = 0; i < 4; i++)
        #pragma unroll
        for (int j = 0; j < 4; j++)
            #pragma unroll
            for (int r = 0; r < 4; r++) acc[i][j][r] = 0.f;

    for (int k0 = 0; k0 < K; k0 += KT) {
        // load tiles (transposed to k-major) with tf32 conversion
        #pragma unroll
        for (int i = 0; i < 4; i++) {
            float4 av = *(const float4*)(Ab + (size_t)lrow * K + k0 + lk + 4 * i);
            float4 bv = *(const float4*)(Bb + (size_t)lrow * K + k0 + lk + 4 * i);
            As[lk + 4 * i + 0][lrow] = f2tf32(av.x);
            As[lk + 4 * i + 1][lrow] = f2tf32(av.y);
            As[lk + 4 * i + 2][lrow] = f2tf32(av.z);
            As[lk + 4 * i + 3][lrow] = f2tf32(av.w);
            Bs[lk + 4 * i + 0][lrow] = f2tf32(bv.x);
            Bs[lk + 4 * i + 1][lrow] = f2tf32(bv.y);
            Bs[lk + 4 * i + 2][lrow] = f2tf32(bv.z);
            Bs[lk + 4 * i + 3][lrow] = f2tf32(bv.w);
        }
        __syncthreads();

        #pragma unroll
        for (int kk = 0; kk < KT / 8; kk++) {
            const int kb = kk * 8;
            unsigned a[4][4], b[4][2];
            #pragma unroll
            for (int mi = 0; mi < 4; mi++) {
                int m = wm + mi * 16 + gid;
                a[mi][0] = As[kb + tig    ][m];
                a[mi][1] = As[kb + tig    ][m + 8];
                a[mi][2] = As[kb + tig + 4][m];
                a[mi][3] = As[kb + tig + 4][m + 8];
            }
            #pragma unroll
            for (int nj = 0; nj < 4; nj++) {
                int n = wn + nj * 8 + gid;
                b[nj][0] = Bs[kb + tig    ][n];
                b[nj][1] = Bs[kb + tig + 4][n];
            }
            #pragma unroll
            for (int mi = 0; mi < 4; mi++)
                #pragma unroll
                for (int nj = 0; nj < 4; nj++)
                    mma_tf32(acc[mi][nj], a[mi][0], a[mi][1], a[mi][2], a[mi][3],
                             b[nj][0], b[nj][1]);
        }
        __syncthreads();
    }

    #pragma unroll
    for (int mi = 0; mi < 4; mi++) {
        #pragma unroll
        for (int nj = 0; nj < 4; nj++) {
            int row = blockIdx.y * 128 + wm + mi * 16 + gid;
            int col = blockIdx.x * 128 + wn + nj * 8 + 2 * tig;
            float b0 = bias ? __ldg(bias + col)     : 0.f;
            float b1 = bias ? __ldg(bias + col + 1) : 0.f;
            *(float2*)(Cb + (size_t)row * N + col) =
                make_float2(acc[mi][nj][0] + b0, acc[mi][nj][1] + b1);
            *(float2*)(Cb + (size_t)(row + 8) * N + col) =
                make_float2(acc[mi][nj][2] + b0, acc[mi][nj][3] + b1);
        }
    }
}

// ---------------------------------------------------------------------------
// C[M,N] = A[M,K] @ B[K,N]. A row-major (K contig), B row-major (N contig).
// ---------------------------------------------------------------------------
__global__ __launch_bounds__(256) void tgemm_nn(
    const float* __restrict__ A, const float* __restrict__ Bm,
    float* __restrict__ C, int K, int N, size_t sA, size_t sB, size_t sC)
{
    __shared__ unsigned As[KT][SPAD];
    __shared__ unsigned Bs[KT][SPAD];

    const float* Ab = A  + (size_t)blockIdx.z * sA + (size_t)blockIdx.y * 128 * K;
    const float* Bb = Bm + (size_t)blockIdx.z * sB + blockIdx.x * 128;
    float*       Cb = C  + (size_t)blockIdx.z * sC;

    const int tid  = threadIdx.x;
    const int lane = tid & 31;
    const int wid  = tid >> 5;
    const int wm   = (wid >> 2) * 64;
    const int wn   = (wid & 3) * 32;
    const int gid  = lane >> 2;
    const int tig  = lane & 3;

    const int arow = tid >> 1;
    const int ak   = (tid & 1) * 16;
    const int bk   = tid >> 5;          // 0..7
    const int bn   = (tid & 31) * 4;    // 0..124

    float acc[4][4][4];
    #pragma unroll
    for (int i = 0; i < 4; i++)
        #pragma unroll
        for (int j = 0; j < 4; j++)
            #pragma unroll
            for (int r = 0; r < 4; r++) acc[i][j][r] = 0.f;

    for (int k0 = 0; k0 < K; k0 += KT) {
        #pragma unroll
        for (int i = 0; i < 4; i++) {
            float4 av = *(const float4*)(Ab + (size_t)arow * K + k0 + ak + 4 * i);
            As[ak + 4 * i + 0][arow] = f2tf32(av.x);
            As[ak + 4 * i + 1][arow] = f2tf32(av.y);
            As[ak + 4 * i + 2][arow] = f2tf32(av.z);
            As[ak + 4 * i + 3][arow] = f2tf32(av.w);
            float4 bv = *(const float4*)(Bb + (size_t)(k0 + bk + 8 * i) * N + bn);
            Bs[bk + 8 * i][bn + 0] = f2tf32(bv.x);
            Bs[bk + 8 * i][bn + 1] = f2tf32(bv.y);
            Bs[bk + 8 * i][bn + 2] = f2tf32(bv.z);
            Bs[bk + 8 * i][bn + 3] = f2tf32(bv.w);
        }
        __syncthreads();

        #pragma unroll
        for (int kk = 0; kk < KT / 8; kk++) {
            const int kb = kk * 8;
            unsigned a[4][4], b[4][2];
            #pragma unroll
            for (int mi = 0; mi < 4; mi++) {
                int m = wm + mi * 16 + gid;
                a[mi][0] = As[kb + tig    ][m];
                a[mi][1] = As[kb + tig    ][m + 8];
                a[mi][2] = As[kb + tig + 4][m];
                a[mi][3] = As[kb + tig + 4][m + 8];
            }
            #pragma unroll
            for (int nj = 0; nj < 4; nj++) {
                int n = wn + nj * 8 + gid;
                b[nj][0] = Bs[kb + tig    ][n];
                b[nj][1] = Bs[kb + tig + 4][n];
            }
            #pragma unroll
            for (int mi = 0; mi < 4; mi++)
                #pragma unroll
                for (int nj = 0; nj < 4; nj++)
                    mma_tf32(acc[mi][nj], a[mi][0], a[mi][1], a[mi][2], a[mi][3],
                             b[nj][0], b[nj][1]);
        }
        __syncthreads();
    }

    #pragma unroll
    for (int mi = 0; mi < 4; mi++) {
        #pragma unroll
        for (int nj = 0; nj < 4; nj++) {
            int row = blockIdx.y * 128 + wm + mi * 16 + gid;
            int col = blockIdx.x * 128 + wn + nj * 8 + 2 * tig;
            *(float2*)(Cb + (size_t)row * N + col) =
                make_float2(acc[mi][nj][0], acc[mi][nj][1]);
            *(float2*)(Cb + (size_t)(row + 8) * N + col) =
                make_float2(acc[mi][nj][2], acc[mi][nj][3]);
        }
    }
}

// ---------------------------------------------------------------------------
// In-place scaled softmax over rows of 512. One warp per row.
// ---------------------------------------------------------------------------
__global__ __launch_bounds__(256) void softmax_rows(float* __restrict__ S, float scale)
{
    const int row  = blockIdx.x * 8 + (threadIdx.x >> 5);
    const int lane = threadIdx.x & 31;
    float4* r4 = (float4*)(S + (size_t)row * LSEQ) + lane;

    float4 v[4];
    #pragma unroll
    for (int i = 0; i < 4; i++) {
        v[i] = r4[32 * i];
        v[i].x *= scale; v[i].y *= scale; v[i].z *= scale; v[i].w *= scale;
    }

    float mx = -3.4e38f;
    #pragma unroll
    for (int i = 0; i < 4; i++)
        mx = fmaxf(mx, fmaxf(fmaxf(v[i].x, v[i].y), fmaxf(v[i].z, v[i].w)));
    #pragma unroll
    for (int o = 16; o > 0; o >>= 1)
        mx = fmaxf(mx, __shfl_xor_sync(0xffffffffu, mx, o));

    float sum = 0.f;
    #pragma unroll
    for (int i = 0; i < 4; i++) {
        v[i].x = __expf(v[i].x - mx); v[i].y = __expf(v[i].y - mx);
        v[i].z = __expf(v[i].z - mx); v[i].w = __expf(v[i].w - mx);
        sum += v[i].x + v[i].y + v[i].z + v[i].w;
    }
    #pragma unroll
    for (int o = 16; o > 0; o >>= 1)
        sum += __shfl_xor_sync(0xffffffffu, sum, o);

    const float inv = 1.0f / sum;
    #pragma unroll
    for (int i = 0; i < 4; i++) {
        v[i].x *= inv; v[i].y *= inv; v[i].z *= inv; v[i].w *= inv;
        r4[32 * i] = v[i];
    }
}

extern "C" void kernel_launch(void* const* d_in, const int* in_sizes, int n_in,
                              void* d_out, int out_size)
{
    const float* q   = (const float*)d_in[0];
    const float* k   = (const float*)d_in[1];
    const float* v   = (const float*)d_in[2];
    const float* q_w = (const float*)d_in[3];
    const float* q_b = (const float*)d_in[4];
    const float* k_w = (const float*)d_in[5];
    const float* k_b = (const float*)d_in[6];
    const float* v_w = (const float*)d_in[7];
    const float* v_b = (const float*)d_in[8];
    float* out = (float*)d_out;

    float *qp, *kp, *vp, *s;
    cudaGetSymbolAddress((void**)&qp, g_qp);
    cudaGetSymbolAddress((void**)&kp, g_kp);
    cudaGetSymbolAddress((void**)&vp, g_vp);
    cudaGetSymbolAddress((void**)&s,  g_s);

    // Projections: C[M,768] = X[M,768] @ W[768,768]^T + b
    tgemm_nt<<<dim3(DIM / 128, (BATCH * NQ) / 128, 1), 256>>>(
        q, q_w, q_b, qp, DIM, DIM, 0, 0, 0);
    tgemm_nt<<<dim3(DIM / 128, (BATCH * LSEQ) / 128, 1), 256>>>(
        k, k_w, k_b, kp, DIM, DIM, 0, 0, 0);
    tgemm_nt<<<dim3(DIM / 128, (BATCH * LSEQ) / 128, 1), 256>>>(
        v, v_w, v_b, vp, DIM, DIM, 0, 0, 0);

    // Scores: S[b] = qp[b] @ kp[b]^T   (1024x512, K=768)
    tgemm_nt<<<dim3(LSEQ / 128, NQ / 128, BATCH), 256>>>(
        qp, kp, nullptr, s, DIM, LSEQ,
        (size_t)NQ * DIM, (size_t)LSEQ * DIM, (size_t)NQ * LSEQ);

    // Softmax, scale = 1/sqrt(768)
    softmax_rows<<<(BATCH * NQ) / 8, 256>>>(s, 0.03608439182435161f);

    // Output: O[b] = P[b] @ vp[b]   (1024x768, K=512)
    tgemm_nn<<<dim3(DIM / 128, NQ / 128, BATCH), 256>>>(
        s, vp, out, LSEQ, DIM,
        (size_t)NQ * LSEQ, (size_t)LSEQ * DIM, (size_t)NQ * DIM);
}